// round 8
// baseline (speedup 1.0000x reference)
#include <cuda_runtime.h>
#include <cstdint>

// Cross attention B=8, Tq=Tk=2048, D=1024, fp32.
// All 6 GEMMs via mma.sync m16n8k8 tf32; fragments loaded with ldmatrix.x4.
// Operands pre-rounded to tf32 (rna) at producers => MMA truncation exact.

#define BATCH 8
#define TSEQ  2048
#define EMB   1024
#define MTOT  (BATCH * TSEQ)          // 16384
#define NELEM ((size_t)MTOT * EMB)    // 16M

// ---------------- scratch (__device__ globals; no allocation) --------------
__device__ float g_T[NELEM];
__device__ float g_Src[NELEM];
__device__ float g_W[4u * EMB * EMB];
__device__ float g_Q[NELEM];
__device__ float g_K[NELEM];
__device__ float g_Vt[NELEM];                        // [B][EMB][TSEQ]
__device__ float g_S[(size_t)BATCH * TSEQ * TSEQ];   // scores -> P in place
__device__ float g_O[NELEM];

// ---------------- helpers --------------------------------------------------
__device__ __forceinline__ uint32_t smem_u32(const void* p) {
    uint32_t a;
    asm("{ .reg .u64 t; cvta.to.shared.u64 t, %1; cvt.u32.u64 %0, t; }" : "=r"(a) : "l"(p));
    return a;
}
__device__ __forceinline__ float tf32r(float x) {
    uint32_t u;
    asm("cvt.rna.tf32.f32 %0, %1;" : "=r"(u) : "f"(x));
    return __uint_as_float(u);
}
#define CP_ASYNC16(dst, src) \
    asm volatile("cp.async.cg.shared.global [%0], [%1], 16;" :: "r"(dst), "l"(src) : "memory")
#define CP_COMMIT() asm volatile("cp.async.commit_group;" ::: "memory")

#define MMA_TF32(c, a, b) \
    asm volatile("mma.sync.aligned.m16n8k8.row.col.f32.tf32.tf32.f32 " \
        "{%0,%1,%2,%3}, {%4,%5,%6,%7}, {%8,%9}, {%0,%1,%2,%3};" \
        : "+f"((c)[0]), "+f"((c)[1]), "+f"((c)[2]), "+f"((c)[3]) \
        : "r"((a)[0]), "r"((a)[1]), "r"((a)[2]), "r"((a)[3]), "r"((b)[0]), "r"((b)[1]))

#define LDSM_X4(d0, d1, d2, d3, a) \
    asm volatile("ldmatrix.sync.aligned.m8n8.x4.shared.b16 {%0,%1,%2,%3}, [%4];" \
        : "=r"(d0), "=r"(d1), "=r"(d2), "=r"(d3) : "r"(a))

// ---------------------------------------------------------------------------
// tf32 GEMM (all-NT): C[M,N] = alpha * A[M,K] @ B[N,K]^T (+ bias[N])
// BM=128 BN=256 BK=32, 256 threads = 8 warps (2 M x 4 N), warp tile 64x64.
// 3-stage cp.async pipeline, 36-float padded rows, ldmatrix fragment loads.
// MODE 0: fp32 out. MODE 1: tf32-rounded out. MODE 2: rounded + transposed
//         (Vt[b][col][tok], b = m0/TSEQ).
// ---------------------------------------------------------------------------
#define BM 128
#define BN 256
#define BK 32
#define STG_FLOATS 13824            // (128+256)*36
#define STG_BYTES  55296
#define GEMM_SMEM  (3 * STG_BYTES)  // 165888

template <int MODE, bool HAS_BIAS>
__global__ __launch_bounds__(256, 1)
void tf32_gemm(const float* __restrict__ A, const float* __restrict__ B,
               const float* __restrict__ bias, float* __restrict__ C,
               int M, int N, int K, float alpha,
               size_t sA, size_t sB, size_t sC)
{
    extern __shared__ float sm[];
    const uint32_t sb = smem_u32(sm);

    const int tid  = threadIdx.x;
    const int wid  = tid >> 5, lane = tid & 31;
    const int g    = lane >> 2, t4 = lane & 3;
    const int wm   = wid & 1,  wn = wid >> 1;

    const int m0 = blockIdx.y * BM;
    const int n0 = blockIdx.x * BN;
    A += (size_t)blockIdx.z * sA + (size_t)m0 * K;
    B += (size_t)blockIdx.z * sB + (size_t)n0 * K;

    auto load_stage = [&](int kt, int s) {
        const uint32_t st = sb + s * STG_BYTES;
        const int k0 = kt * BK;
#pragma unroll
        for (int i = 0; i < 4; i++) {          // A: 128 rows x 8 chunks
            int id = tid + i * 256, r = id >> 3, c = id & 7;
            CP_ASYNC16(st + (r * 36 + c * 4) * 4, A + (size_t)r * K + k0 + c * 4);
        }
#pragma unroll
        for (int i = 0; i < 8; i++) {          // B: 256 rows x 8 chunks
            int id = tid + i * 256, r = id >> 3, c = id & 7;
            CP_ASYNC16(st + 18432 + (r * 36 + c * 4) * 4, B + (size_t)r * K + k0 + c * 4);
        }
        CP_COMMIT();
    };

    // ldmatrix lane address offsets (within a stage), in bytes:
    //   lanes 0-7: row r, colgrp 0 | 8-15: row r+8, colgrp 0
    //   lanes 16-23: row r, colgrp 1 | 24-31: row r+8, colgrp 1
    const int lrow = (lane & 7) + ((lane >> 3) & 1) * 8;
    const int lcg  = (lane >> 4) * 4;
    const uint32_t aOff = ((wm * 64 + lrow) * 36 + lcg) * 4;
    const uint32_t bOff = 18432 + ((wn * 64 + lrow) * 36 + lcg) * 4;

    float acc[4][8][4];
#pragma unroll
    for (int mi = 0; mi < 4; mi++)
#pragma unroll
        for (int ni = 0; ni < 8; ni++)
#pragma unroll
            for (int r = 0; r < 4; r++) acc[mi][ni][r] = 0.0f;

    const int KT = K / BK;
    load_stage(0, 0);
    load_stage(1, 1);
    load_stage(2, 2);

    for (int kt = 0; kt < KT; kt++) {
        asm volatile("cp.async.wait_group 2;" ::: "memory");
        __syncthreads();
        const int s = kt % 3;
        const uint32_t stg = sb + s * STG_BYTES;
        const uint32_t aAddr = stg + aOff;
        const uint32_t bAddr = stg + bOff;

#pragma unroll
        for (int ks = 0; ks < 4; ks++) {
            uint32_t af[4][4], bf[8][2];
#pragma unroll
            for (int mi = 0; mi < 4; mi++)
                LDSM_X4(af[mi][0], af[mi][1], af[mi][2], af[mi][3],
                        aAddr + mi * (16 * 36 * 4) + ks * 32);
#pragma unroll
            for (int nip = 0; nip < 4; nip++)
                LDSM_X4(bf[2 * nip][0], bf[2 * nip + 1][0],
                        bf[2 * nip][1], bf[2 * nip + 1][1],
                        bAddr + nip * (16 * 36 * 4) + ks * 32);
#pragma unroll
            for (int mi = 0; mi < 4; mi++)
#pragma unroll
                for (int ni = 0; ni < 8; ni++)
                    MMA_TF32(acc[mi][ni], af[mi], bf[ni]);
        }
        __syncthreads();
        if (kt + 3 < KT) load_stage(kt + 3, s);
    }

    // ---- epilogue ----
    if (MODE == 2) {
        float* Cb = C + (size_t)(m0 / TSEQ) * EMB * TSEQ;
        const int tokbase = (m0 % TSEQ) + wm * 64 + g;
#pragma unroll
        for (int mi = 0; mi < 4; mi++) {
            const int tok = tokbase + mi * 16;
#pragma unroll
            for (int ni = 0; ni < 8; ni++) {
                const int col = n0 + wn * 64 + ni * 8 + t4 * 2;
                float b0 = HAS_BIAS ? __ldg(bias + col)     : 0.0f;
                float b1 = HAS_BIAS ? __ldg(bias + col + 1) : 0.0f;
                Cb[(size_t)col * TSEQ + tok]           = tf32r(acc[mi][ni][0] * alpha + b0);
                Cb[(size_t)(col + 1) * TSEQ + tok]     = tf32r(acc[mi][ni][1] * alpha + b1);
                Cb[(size_t)col * TSEQ + tok + 8]       = tf32r(acc[mi][ni][2] * alpha + b0);
                Cb[(size_t)(col + 1) * TSEQ + tok + 8] = tf32r(acc[mi][ni][3] * alpha + b1);
            }
        }
    } else {
        C += (size_t)blockIdx.z * sC;
#pragma unroll
        for (int mi = 0; mi < 4; mi++) {
            const int row = m0 + wm * 64 + mi * 16 + g;
#pragma unroll
            for (int ni = 0; ni < 8; ni++) {
                const int col = n0 + wn * 64 + ni * 8 + t4 * 2;
                float b0 = HAS_BIAS ? __ldg(bias + col)     : 0.0f;
                float b1 = HAS_BIAS ? __ldg(bias + col + 1) : 0.0f;
                float f0 = acc[mi][ni][0] * alpha + b0;
                float f1 = acc[mi][ni][1] * alpha + b1;
                float f2 = acc[mi][ni][2] * alpha + b0;
                float f3 = acc[mi][ni][3] * alpha + b1;
                if (MODE == 1) { f0 = tf32r(f0); f1 = tf32r(f1); f2 = tf32r(f2); f3 = tf32r(f3); }
                *reinterpret_cast<float2*>(C + (size_t)row * N + col)       = make_float2(f0, f1);
                *reinterpret_cast<float2*>(C + (size_t)(row + 8) * N + col) = make_float2(f2, f3);
            }
        }
    }
}

// ---------------------------------------------------------------------------
// tf32 rounding passes (merged: 2 launches total, so ncu -s 5 lands on QK^T)
// ---------------------------------------------------------------------------
__global__ void round_act_kernel(const float4* __restrict__ a, float4* __restrict__ ya,
                                 const float4* __restrict__ b, float4* __restrict__ yb,
                                 int n4)
{
    int i = blockIdx.x * blockDim.x + threadIdx.x;
    if (i >= n4) return;
    const float4* x = blockIdx.y ? b : a;
    float4*       y = blockIdx.y ? yb : ya;
    float4 v = x[i];
    v.x = tf32r(v.x); v.y = tf32r(v.y); v.z = tf32r(v.z); v.w = tf32r(v.w);
    y[i] = v;
}

__global__ void round_w_kernel(const float4* __restrict__ w0, const float4* __restrict__ w1,
                               const float4* __restrict__ w2, const float4* __restrict__ w3,
                               float4* __restrict__ y, int n4)
{
    int i = blockIdx.x * blockDim.x + threadIdx.x;
    if (i >= n4) return;
    const float4* src = (blockIdx.y == 0) ? w0 : (blockIdx.y == 1) ? w1
                      : (blockIdx.y == 2) ? w2 : w3;
    float4 v = src[i];
    v.x = tf32r(v.x); v.y = tf32r(v.y); v.z = tf32r(v.z); v.w = tf32r(v.w);
    y[(size_t)blockIdx.y * n4 + i] = v;
}

// ---------------------------------------------------------------------------
// softmax over 2048-length rows (in place), output tf32-rounded
// ---------------------------------------------------------------------------
__device__ __forceinline__ float blk_red_max(float v) {
    __shared__ float sh[8]; __shared__ float res;
    const int lane = threadIdx.x & 31, warp = threadIdx.x >> 5;
#pragma unroll
    for (int o = 16; o > 0; o >>= 1) v = fmaxf(v, __shfl_xor_sync(0xffffffffu, v, o));
    if (lane == 0) sh[warp] = v;
    __syncthreads();
    if (warp == 0) {
        float w = (lane < 8) ? sh[lane] : -3.0e38f;
#pragma unroll
        for (int o = 4; o > 0; o >>= 1) w = fmaxf(w, __shfl_xor_sync(0xffffffffu, w, o));
        if (lane == 0) res = w;
    }
    __syncthreads();
    return res;
}
__device__ __forceinline__ float blk_red_sum(float v) {
    __shared__ float sh[8]; __shared__ float res;
    const int lane = threadIdx.x & 31, warp = threadIdx.x >> 5;
#pragma unroll
    for (int o = 16; o > 0; o >>= 1) v += __shfl_xor_sync(0xffffffffu, v, o);
    if (lane == 0) sh[warp] = v;
    __syncthreads();
    if (warp == 0) {
        float w = (lane < 8) ? sh[lane] : 0.0f;
#pragma unroll
        for (int o = 4; o > 0; o >>= 1) w += __shfl_xor_sync(0xffffffffu, w, o);
        if (lane == 0) res = w;
    }
    __syncthreads();
    return res;
}

__global__ __launch_bounds__(256)
void softmax_kernel(float* __restrict__ S)
{
    float4* row = reinterpret_cast<float4*>(S + (size_t)blockIdx.x * TSEQ);
    const int t = threadIdx.x;

    float4 v0 = row[t];
    float4 v1 = row[t + 256];

    float mx = fmaxf(fmaxf(fmaxf(v0.x, v0.y), fmaxf(v0.z, v0.w)),
                     fmaxf(fmaxf(v1.x, v1.y), fmaxf(v1.z, v1.w)));
    mx = blk_red_max(mx);

    v0.x = __expf(v0.x - mx); v0.y = __expf(v0.y - mx);
    v0.z = __expf(v0.z - mx); v0.w = __expf(v0.w - mx);
    v1.x = __expf(v1.x - mx); v1.y = __expf(v1.y - mx);
    v1.z = __expf(v1.z - mx); v1.w = __expf(v1.w - mx);

    float s = (v0.x + v0.y + v0.z + v0.w) + (v1.x + v1.y + v1.z + v1.w);
    s = blk_red_sum(s);
    const float inv = 1.0f / s;

    v0.x = tf32r(v0.x * inv); v0.y = tf32r(v0.y * inv);
    v0.z = tf32r(v0.z * inv); v0.w = tf32r(v0.w * inv);
    v1.x = tf32r(v1.x * inv); v1.y = tf32r(v1.y * inv);
    v1.z = tf32r(v1.z * inv); v1.w = tf32r(v1.w * inv);
    row[t]       = v0;
    row[t + 256] = v1;
}

// ---------------------------------------------------------------------------
extern "C" void kernel_launch(void* const* d_in, const int* in_sizes, int n_in,
                              void* d_out, int out_size)
{
    const float* target = (const float*)d_in[0];
    const float* source = (const float*)d_in[1];
    const float* Wq = (const float*)d_in[2];
    const float* bq = (const float*)d_in[3];
    const float* Wk = (const float*)d_in[4];
    const float* bk = (const float*)d_in[5];
    const float* Wv = (const float*)d_in[6];
    const float* bv = (const float*)d_in[7];
    const float* Wo = (const float*)d_in[8];
    const float* bo = (const float*)d_in[9];
    float* out = (float*)d_out;

    float *T, *Src, *W, *Q, *Kb, *Vt, *S, *O;
    cudaGetSymbolAddress((void**)&T,   g_T);
    cudaGetSymbolAddress((void**)&Src, g_Src);
    cudaGetSymbolAddress((void**)&W,   g_W);
    cudaGetSymbolAddress((void**)&Q,   g_Q);
    cudaGetSymbolAddress((void**)&Kb,  g_K);
    cudaGetSymbolAddress((void**)&Vt,  g_Vt);
    cudaGetSymbolAddress((void**)&S,   g_S);
    cudaGetSymbolAddress((void**)&O,   g_O);

    cudaFuncSetAttribute(tf32_gemm<0, false>, cudaFuncAttributeMaxDynamicSharedMemorySize, GEMM_SMEM);
    cudaFuncSetAttribute(tf32_gemm<0, true>,  cudaFuncAttributeMaxDynamicSharedMemorySize, GEMM_SMEM);
    cudaFuncSetAttribute(tf32_gemm<1, false>, cudaFuncAttributeMaxDynamicSharedMemorySize, GEMM_SMEM);
    cudaFuncSetAttribute(tf32_gemm<1, true>,  cudaFuncAttributeMaxDynamicSharedMemorySize, GEMM_SMEM);
    cudaFuncSetAttribute(tf32_gemm<2, true>,  cudaFuncAttributeMaxDynamicSharedMemorySize, GEMM_SMEM);

    // launch 0: round both activations; launch 1: round 4 weights
    {
        dim3 ga((unsigned)(NELEM / 4 / 256), 2, 1);
        round_act_kernel<<<ga, 256>>>((const float4*)target, (float4*)T,
                                      (const float4*)source, (float4*)Src,
                                      (int)(NELEM / 4));
        dim3 gw((unsigned)(EMB * EMB / 4 / 256), 4, 1);
        round_w_kernel<<<gw, 256>>>((const float4*)Wq, (const float4*)Wk,
                                    (const float4*)Wv, (const float4*)Wo,
                                    (float4*)W, EMB * EMB / 4);
    }

    const float scale = 1.0f / 32.0f;  // 1/sqrt(1024)

    // launches 2-4: projections (rounded outputs)
    {
        dim3 grd(EMB / BN, MTOT / BM, 1);
        tf32_gemm<1, true><<<grd, 256, GEMM_SMEM>>>(T,   W + 0u * EMB * EMB, bq, Q,
                                                    MTOT, EMB, EMB, 1.0f, 0, 0, 0);
        tf32_gemm<1, true><<<grd, 256, GEMM_SMEM>>>(Src, W + 1u * EMB * EMB, bk, Kb,
                                                    MTOT, EMB, EMB, 1.0f, 0, 0, 0);
        tf32_gemm<2, true><<<grd, 256, GEMM_SMEM>>>(Src, W + 2u * EMB * EMB, bv, Vt,
                                                    MTOT, EMB, EMB, 1.0f, 0, 0, 0);
    }

    // launch 5 (ncu -s 5 -c 1 captures this): S = Q @ K^T / 32
    {
        dim3 grd(TSEQ / BN, TSEQ / BM, BATCH);
        tf32_gemm<0, false><<<grd, 256, GEMM_SMEM>>>(Q, Kb, nullptr, S,
            TSEQ, TSEQ, EMB, scale,
            (size_t)TSEQ * EMB, (size_t)TSEQ * EMB, (size_t)TSEQ * TSEQ);
    }

    // P = softmax(S), tf32-rounded, in place
    softmax_kernel<<<BATCH * TSEQ, 256>>>(S);

    // O = P @ Vt^T (batched, K=2048)
    {
        dim3 grd(EMB / BN, TSEQ / BM, BATCH);
        tf32_gemm<1, false><<<grd, 256, GEMM_SMEM>>>(S, Vt, nullptr, O,
            TSEQ, EMB, TSEQ, 1.0f,
            (size_t)TSEQ * TSEQ, (size_t)EMB * TSEQ, (size_t)TSEQ * EMB);
    }

    // out = O @ Wo^T + bo (fp32)
    {
        dim3 grd(EMB / BN, MTOT / BM, 1);
        tf32_gemm<0, true><<<grd, 256, GEMM_SMEM>>>(O, W + 3u * EMB * EMB, bo, out,
                                                    MTOT, EMB, EMB, 1.0f, 0, 0, 0);
    }
}

// round 9
// speedup vs baseline: 1.1280x; 1.1280x over previous
#include <cuda_runtime.h>
#include <cstdint>

// Cross attention B=8, Tq=Tk=2048, D=1024, fp32.
// All 6 GEMMs via mma.sync m16n8k8 tf32. K-dim stored PERMUTED (p8: within
// each 8-block, order k,k+4 interleaved) so fragment loads are LDS.64.
// Operands pre-rounded to tf32 (rna) at producers => MMA truncation exact.

#define BATCH 8
#define TSEQ  2048
#define EMB   1024
#define MTOT  (BATCH * TSEQ)          // 16384
#define NELEM ((size_t)MTOT * EMB)    // 16M

// ---------------- scratch (__device__ globals; no allocation) --------------
__device__ float g_T[NELEM];
__device__ float g_Src[NELEM];
__device__ float g_W[4u * EMB * EMB];
__device__ float g_Q[NELEM];
__device__ float g_K[NELEM];
__device__ float g_Vt[NELEM];                        // [B][EMB][TSEQ]
__device__ float g_S[(size_t)BATCH * TSEQ * TSEQ];   // scores -> P in place
__device__ float g_O[NELEM];

// ---------------- helpers --------------------------------------------------
__device__ __forceinline__ uint32_t smem_u32(const void* p) {
    uint32_t a;
    asm("{ .reg .u64 t; cvta.to.shared.u64 t, %1; cvt.u32.u64 %0, t; }" : "=r"(a) : "l"(p));
    return a;
}
__device__ __forceinline__ float tf32r(float x) {
    uint32_t u;
    asm("cvt.rna.tf32.f32 %0, %1;" : "=r"(u) : "f"(x));
    return __uint_as_float(u);
}
// position of true index c under the k-permutation (within its 8-block)
__device__ __forceinline__ int p8(int c) {
    return (c & ~7) | ((c & 3) << 1) | ((c >> 2) & 1);
}
#define CP_ASYNC16(dst, src) \
    asm volatile("cp.async.cg.shared.global [%0], [%1], 16;" :: "r"(dst), "l"(src) : "memory")
#define CP_COMMIT() asm volatile("cp.async.commit_group;" ::: "memory")
#define CP_WAIT1()  asm volatile("cp.async.wait_group 1;" ::: "memory")
#define CP_WAIT0()  asm volatile("cp.async.wait_group 0;" ::: "memory")

#define MMA_TF32(c, a, b) \
    asm volatile("mma.sync.aligned.m16n8k8.row.col.f32.tf32.tf32.f32 " \
        "{%0,%1,%2,%3}, {%4,%5,%6,%7}, {%8,%9}, {%0,%1,%2,%3};" \
        : "+f"((c)[0]), "+f"((c)[1]), "+f"((c)[2]), "+f"((c)[3]) \
        : "r"((a)[0]), "r"((a)[1]), "r"((a)[2]), "r"((a)[3]), "r"((b)[0]), "r"((b)[1]))

// ---------------------------------------------------------------------------
// tf32 GEMM (all-NT): C[M,N] = alpha * A[M,K] @ B[N,K]^T (+ bias[N])
// A,B stored with k-dim permuted by p8. BM=128 BN=256 BK=32, 256 threads =
// 8 warps (2 M x 4 N), warp tile 64x64. 3-stage cp.async ring, prefetch
// distance 2, ONE __syncthreads per iteration. Rows padded to 40 floats
// (LDS.64 lane words 8g+2*t4 mod 32 -> all banks distinct).
// MODE 0: fp32 out (true col order). MODE 1: tf32-rounded out, cols stored
// p8-permuted. MODE 2: rounded + transposed (Vt[b][col][p8(tok)]).
// ---------------------------------------------------------------------------
#define BM 128
#define BN 256
#define BK 32
#define ROWW 40
#define STG_FLOATS ((BM + BN) * ROWW)   // 15360
#define STG_BYTES  (STG_FLOATS * 4)     // 61440
#define GEMM_SMEM  (3 * STG_BYTES)      // 184320

template <int MODE, bool HAS_BIAS>
__global__ __launch_bounds__(256, 1)
void tf32_gemm(const float* __restrict__ A, const float* __restrict__ B,
               const float* __restrict__ bias, float* __restrict__ C,
               int M, int N, int K, float alpha,
               size_t sA, size_t sB, size_t sC)
{
    extern __shared__ float sm[];
    const uint32_t sb = smem_u32(sm);

    const int tid  = threadIdx.x;
    const int wid  = tid >> 5, lane = tid & 31;
    const int g    = lane >> 2, t4 = lane & 3;
    const int wm   = wid & 1,  wn = wid >> 1;

    const int m0 = blockIdx.y * BM;
    const int n0 = blockIdx.x * BN;
    A += (size_t)blockIdx.z * sA + (size_t)m0 * K;
    B += (size_t)blockIdx.z * sB + (size_t)n0 * K;

    auto load_stage = [&](int kt, int s) {
        const uint32_t st = sb + s * STG_BYTES;
        const int k0 = kt * BK;
#pragma unroll
        for (int i = 0; i < 4; i++) {          // A: 128 rows x 8 chunks
            int id = tid + i * 256, r = id >> 3, c = id & 7;
            CP_ASYNC16(st + (r * ROWW + c * 4) * 4, A + (size_t)r * K + k0 + c * 4);
        }
#pragma unroll
        for (int i = 0; i < 8; i++) {          // B: 256 rows x 8 chunks
            int id = tid + i * 256, r = id >> 3, c = id & 7;
            CP_ASYNC16(st + (BM * ROWW + r * ROWW + c * 4) * 4,
                       B + (size_t)r * K + k0 + c * 4);
        }
        CP_COMMIT();
    };

    // fragment base pointers (k-permuted layout: word 2*t4 holds k=t4,t4+4)
    const float* aBase = sm + (wm * 64 + g) * ROWW + 2 * t4;
    const float* bBase = sm + BM * ROWW + (wn * 64 + g) * ROWW + 2 * t4;

    float acc[4][8][4];
#pragma unroll
    for (int mi = 0; mi < 4; mi++)
#pragma unroll
        for (int ni = 0; ni < 8; ni++)
#pragma unroll
            for (int r = 0; r < 4; r++) acc[mi][ni][r] = 0.0f;

    const int KT = K / BK;
    load_stage(0, 0);
    load_stage(1, 1);

    for (int kt = 0; kt < KT; kt++) {
        if (kt + 1 < KT) { CP_WAIT1(); } else { CP_WAIT0(); }
        __syncthreads();
        if (kt + 2 < KT) load_stage(kt + 2, (kt + 2) % 3);

        const float* As = aBase + (kt % 3) * STG_FLOATS;
        const float* Bs = bBase + (kt % 3) * STG_FLOATS;

#pragma unroll
        for (int ks = 0; ks < 4; ks++) {
            uint32_t af[4][4], bf[8][2];
#pragma unroll
            for (int mi = 0; mi < 4; mi++) {
                float2 lo = *reinterpret_cast<const float2*>(As + mi * 16 * ROWW + ks * 8);
                float2 hi = *reinterpret_cast<const float2*>(As + mi * 16 * ROWW + 8 * ROWW + ks * 8);
                af[mi][0] = __float_as_uint(lo.x);
                af[mi][1] = __float_as_uint(hi.x);
                af[mi][2] = __float_as_uint(lo.y);
                af[mi][3] = __float_as_uint(hi.y);
            }
#pragma unroll
            for (int ni = 0; ni < 8; ni++) {
                float2 b = *reinterpret_cast<const float2*>(Bs + ni * 8 * ROWW + ks * 8);
                bf[ni][0] = __float_as_uint(b.x);
                bf[ni][1] = __float_as_uint(b.y);
            }
#pragma unroll
            for (int mi = 0; mi < 4; mi++)
#pragma unroll
                for (int ni = 0; ni < 8; ni++)
                    MMA_TF32(acc[mi][ni], af[mi], bf[ni]);
        }
    }

    // ---- epilogue ----
    if (MODE == 2) {
        // transposed + rounded: Vt[b][col][p8(tok)]
        float* Cb = C + (size_t)(m0 / TSEQ) * EMB * TSEQ;
        const int pg = ((g & 3) << 1) | (g >> 2);
        const int tokbase = (m0 % TSEQ) + wm * 64 + pg;
#pragma unroll
        for (int mi = 0; mi < 4; mi++) {
            const int tok = tokbase + mi * 16;         // already permuted low bits
#pragma unroll
            for (int ni = 0; ni < 8; ni++) {
                const int col = n0 + wn * 64 + ni * 8 + t4 * 2;
                float b0 = HAS_BIAS ? __ldg(bias + col)     : 0.0f;
                float b1 = HAS_BIAS ? __ldg(bias + col + 1) : 0.0f;
                Cb[(size_t)col * TSEQ + tok]           = tf32r(acc[mi][ni][0] * alpha + b0);
                Cb[(size_t)(col + 1) * TSEQ + tok]     = tf32r(acc[mi][ni][1] * alpha + b1);
                Cb[(size_t)col * TSEQ + tok + 8]       = tf32r(acc[mi][ni][2] * alpha + b0);
                Cb[(size_t)(col + 1) * TSEQ + tok + 8] = tf32r(acc[mi][ni][3] * alpha + b1);
            }
        }
    } else if (MODE == 1) {
        // rounded out, columns stored permuted (they are a k-dim downstream)
        C += (size_t)blockIdx.z * sC;
        const int q0 = ((2 * t4 & 3) << 1) | ((2 * t4) >> 2);        // p8 of 2*t4 in-block
        const int q1 = (((2 * t4 + 1) & 3) << 1) | ((2 * t4 + 1) >> 2);
#pragma unroll
        for (int mi = 0; mi < 4; mi++) {
            const int row = m0 + wm * 64 + mi * 16 + g;
#pragma unroll
            for (int ni = 0; ni < 8; ni++) {
                const int colb = n0 + wn * 64 + ni * 8;
                float b0 = HAS_BIAS ? __ldg(bias + colb + 2 * t4)     : 0.0f;
                float b1 = HAS_BIAS ? __ldg(bias + colb + 2 * t4 + 1) : 0.0f;
                C[(size_t)row * N + colb + q0]       = tf32r(acc[mi][ni][0] * alpha + b0);
                C[(size_t)row * N + colb + q1]       = tf32r(acc[mi][ni][1] * alpha + b1);
                C[(size_t)(row + 8) * N + colb + q0] = tf32r(acc[mi][ni][2] * alpha + b0);
                C[(size_t)(row + 8) * N + colb + q1] = tf32r(acc[mi][ni][3] * alpha + b1);
            }
        }
    } else {
        // MODE 0: plain fp32, true column order
        C += (size_t)blockIdx.z * sC;
#pragma unroll
        for (int mi = 0; mi < 4; mi++) {
            const int row = m0 + wm * 64 + mi * 16 + g;
#pragma unroll
            for (int ni = 0; ni < 8; ni++) {
                const int col = n0 + wn * 64 + ni * 8 + t4 * 2;
                float b0 = HAS_BIAS ? __ldg(bias + col)     : 0.0f;
                float b1 = HAS_BIAS ? __ldg(bias + col + 1) : 0.0f;
                float f0 = acc[mi][ni][0] * alpha + b0;
                float f1 = acc[mi][ni][1] * alpha + b1;
                float f2 = acc[mi][ni][2] * alpha + b0;
                float f3 = acc[mi][ni][3] * alpha + b1;
                *reinterpret_cast<float2*>(C + (size_t)row * N + col)       = make_float2(f0, f1);
                *reinterpret_cast<float2*>(C + (size_t)(row + 8) * N + col) = make_float2(f2, f3);
            }
        }
    }
}

// ---------------------------------------------------------------------------
// rounding passes: tf32-round AND k-permute (8 elements per thread)
// out positions within 8-block: [e0,e4,e1,e5,e2,e6,e3,e7]
// ---------------------------------------------------------------------------
__device__ __forceinline__ void round_perm8(float4 i0, float4 i1,
                                            float4& o0, float4& o1)
{
    o0 = make_float4(tf32r(i0.x), tf32r(i1.x), tf32r(i0.y), tf32r(i1.y));
    o1 = make_float4(tf32r(i0.z), tf32r(i1.z), tf32r(i0.w), tf32r(i1.w));
}

__global__ void round_act_kernel(const float4* __restrict__ a, float4* __restrict__ ya,
                                 const float4* __restrict__ b, float4* __restrict__ yb,
                                 int n8)
{
    int i = blockIdx.x * blockDim.x + threadIdx.x;
    if (i >= n8) return;
    const float4* x = blockIdx.y ? b : a;
    float4*       y = blockIdx.y ? yb : ya;
    float4 o0, o1;
    round_perm8(x[2 * i], x[2 * i + 1], o0, o1);
    y[2 * i] = o0; y[2 * i + 1] = o1;
}

__global__ void round_w_kernel(const float4* __restrict__ w0, const float4* __restrict__ w1,
                               const float4* __restrict__ w2, const float4* __restrict__ w3,
                               float4* __restrict__ y, int n8)
{
    int i = blockIdx.x * blockDim.x + threadIdx.x;
    if (i >= n8) return;
    const float4* src = (blockIdx.y == 0) ? w0 : (blockIdx.y == 1) ? w1
                      : (blockIdx.y == 2) ? w2 : w3;
    float4 o0, o1;
    round_perm8(src[2 * i], src[2 * i + 1], o0, o1);
    y[(size_t)blockIdx.y * 2 * n8 + 2 * i]     = o0;
    y[(size_t)blockIdx.y * 2 * n8 + 2 * i + 1] = o1;
}

// ---------------------------------------------------------------------------
// softmax over 2048-length rows (in place): reads true-order S, writes
// tf32-rounded P with k-permuted columns. 8 elements per thread.
// ---------------------------------------------------------------------------
__device__ __forceinline__ float blk_red_max(float v) {
    __shared__ float sh[8]; __shared__ float res;
    const int lane = threadIdx.x & 31, warp = threadIdx.x >> 5;
#pragma unroll
    for (int o = 16; o > 0; o >>= 1) v = fmaxf(v, __shfl_xor_sync(0xffffffffu, v, o));
    if (lane == 0) sh[warp] = v;
    __syncthreads();
    if (warp == 0) {
        float w = (lane < 8) ? sh[lane] : -3.0e38f;
#pragma unroll
        for (int o = 4; o > 0; o >>= 1) w = fmaxf(w, __shfl_xor_sync(0xffffffffu, w, o));
        if (lane == 0) res = w;
    }
    __syncthreads();
    return res;
}
__device__ __forceinline__ float blk_red_sum(float v) {
    __shared__ float sh[8]; __shared__ float res;
    const int lane = threadIdx.x & 31, warp = threadIdx.x >> 5;
#pragma unroll
    for (int o = 16; o > 0; o >>= 1) v += __shfl_xor_sync(0xffffffffu, v, o);
    if (lane == 0) sh[warp] = v;
    __syncthreads();
    if (warp == 0) {
        float w = (lane < 8) ? sh[lane] : 0.0f;
#pragma unroll
        for (int o = 4; o > 0; o >>= 1) w += __shfl_xor_sync(0xffffffffu, w, o);
        if (lane == 0) res = w;
    }
    __syncthreads();
    return res;
}

__global__ __launch_bounds__(256)
void softmax_kernel(float* __restrict__ S)
{
    float4* row = reinterpret_cast<float4*>(S + (size_t)blockIdx.x * TSEQ);
    const int t = threadIdx.x;

    float4 v0 = row[2 * t];       // elements 8t .. 8t+3
    float4 v1 = row[2 * t + 1];   // elements 8t+4 .. 8t+7

    float mx = fmaxf(fmaxf(fmaxf(v0.x, v0.y), fmaxf(v0.z, v0.w)),
                     fmaxf(fmaxf(v1.x, v1.y), fmaxf(v1.z, v1.w)));
    mx = blk_red_max(mx);

    v0.x = __expf(v0.x - mx); v0.y = __expf(v0.y - mx);
    v0.z = __expf(v0.z - mx); v0.w = __expf(v0.w - mx);
    v1.x = __expf(v1.x - mx); v1.y = __expf(v1.y - mx);
    v1.z = __expf(v1.z - mx); v1.w = __expf(v1.w - mx);

    float s = (v0.x + v0.y + v0.z + v0.w) + (v1.x + v1.y + v1.z + v1.w);
    s = blk_red_sum(s);
    const float inv = 1.0f / s;

    v0.x *= inv; v0.y *= inv; v0.z *= inv; v0.w *= inv;
    v1.x *= inv; v1.y *= inv; v1.z *= inv; v1.w *= inv;

    float4 o0, o1;
    round_perm8(v0, v1, o0, o1);
    row[2 * t]     = o0;
    row[2 * t + 1] = o1;
}

// ---------------------------------------------------------------------------
extern "C" void kernel_launch(void* const* d_in, const int* in_sizes, int n_in,
                              void* d_out, int out_size)
{
    const float* target = (const float*)d_in[0];
    const float* source = (const float*)d_in[1];
    const float* Wq = (const float*)d_in[2];
    const float* bq = (const float*)d_in[3];
    const float* Wk = (const float*)d_in[4];
    const float* bk = (const float*)d_in[5];
    const float* Wv = (const float*)d_in[6];
    const float* bv = (const float*)d_in[7];
    const float* Wo = (const float*)d_in[8];
    const float* bo = (const float*)d_in[9];
    float* out = (float*)d_out;

    float *T, *Src, *W, *Q, *Kb, *Vt, *S, *O;
    cudaGetSymbolAddress((void**)&T,   g_T);
    cudaGetSymbolAddress((void**)&Src, g_Src);
    cudaGetSymbolAddress((void**)&W,   g_W);
    cudaGetSymbolAddress((void**)&Q,   g_Q);
    cudaGetSymbolAddress((void**)&Kb,  g_K);
    cudaGetSymbolAddress((void**)&Vt,  g_Vt);
    cudaGetSymbolAddress((void**)&S,   g_S);
    cudaGetSymbolAddress((void**)&O,   g_O);

    cudaFuncSetAttribute(tf32_gemm<0, false>, cudaFuncAttributeMaxDynamicSharedMemorySize, GEMM_SMEM);
    cudaFuncSetAttribute(tf32_gemm<0, true>,  cudaFuncAttributeMaxDynamicSharedMemorySize, GEMM_SMEM);
    cudaFuncSetAttribute(tf32_gemm<1, false>, cudaFuncAttributeMaxDynamicSharedMemorySize, GEMM_SMEM);
    cudaFuncSetAttribute(tf32_gemm<1, true>,  cudaFuncAttributeMaxDynamicSharedMemorySize, GEMM_SMEM);
    cudaFuncSetAttribute(tf32_gemm<2, true>,  cudaFuncAttributeMaxDynamicSharedMemorySize, GEMM_SMEM);

    // launch 0: round+perm both activations; launch 1: round+perm 4 weights
    {
        dim3 ga((unsigned)(NELEM / 8 / 256), 2, 1);
        round_act_kernel<<<ga, 256>>>((const float4*)target, (float4*)T,
                                      (const float4*)source, (float4*)Src,
                                      (int)(NELEM / 8));
        dim3 gw((unsigned)(EMB * EMB / 8 / 256), 4, 1);
        round_w_kernel<<<gw, 256>>>((const float4*)Wq, (const float4*)Wk,
                                    (const float4*)Wv, (const float4*)Wo,
                                    (float4*)W, EMB * EMB / 8);
    }

    const float scale = 1.0f / 32.0f;  // 1/sqrt(1024)

    // launches 2-4: projections
    {
        dim3 grd(EMB / BN, MTOT / BM, 1);
        tf32_gemm<1, true><<<grd, 256, GEMM_SMEM>>>(T,   W + 0u * EMB * EMB, bq, Q,
                                                    MTOT, EMB, EMB, 1.0f, 0, 0, 0);
        tf32_gemm<1, true><<<grd, 256, GEMM_SMEM>>>(Src, W + 1u * EMB * EMB, bk, Kb,
                                                    MTOT, EMB, EMB, 1.0f, 0, 0, 0);
        tf32_gemm<2, true><<<grd, 256, GEMM_SMEM>>>(Src, W + 2u * EMB * EMB, bv, Vt,
                                                    MTOT, EMB, EMB, 1.0f, 0, 0, 0);
    }

    // launch 5 (ncu -s 5 -c 1 captures this): S = Q @ K^T / 32
    {
        dim3 grd(TSEQ / BN, TSEQ / BM, BATCH);
        tf32_gemm<0, false><<<grd, 256, GEMM_SMEM>>>(Q, Kb, nullptr, S,
            TSEQ, TSEQ, EMB, scale,
            (size_t)TSEQ * EMB, (size_t)TSEQ * EMB, (size_t)TSEQ * TSEQ);
    }

    // P = softmax(S) in place (rounded + k-permuted)
    softmax_kernel<<<BATCH * TSEQ, 256>>>(S);

    // O = P @ Vt^T (batched, K=2048)
    {
        dim3 grd(EMB / BN, TSEQ / BM, BATCH);
        tf32_gemm<1, false><<<grd, 256, GEMM_SMEM>>>(S, Vt, nullptr, O,
            TSEQ, EMB, TSEQ, 1.0f,
            (size_t)TSEQ * TSEQ, (size_t)EMB * TSEQ, (size_t)TSEQ * EMB);
    }

    // out = O @ Wo^T + bo (fp32, true order)
    {
        dim3 grd(EMB / BN, MTOT / BM, 1);
        tf32_gemm<0, true><<<grd, 256, GEMM_SMEM>>>(O, W + 3u * EMB * EMB, bo, out,
                                                    MTOT, EMB, EMB, 1.0f, 0, 0, 0);
    }
}

// round 10
// speedup vs baseline: 1.2588x; 1.1159x over previous
#include <cuda_runtime.h>
#include <cstdint>

// Cross attention B=8, Tq=Tk=2048, D=1024, fp32.
// All 6 GEMMs via mma.sync m16n8k8 tf32. K-dim stored PERMUTED (p8) so
// fragment loads are LDS.64. 128x128 tiles, 2 CTAs/SM for latency hiding.

#define BATCH 8
#define TSEQ  2048
#define EMB   1024
#define MTOT  (BATCH * TSEQ)          // 16384
#define NELEM ((size_t)MTOT * EMB)    // 16M

// ---------------- scratch (__device__ globals; no allocation) --------------
__device__ float g_T[NELEM];
__device__ float g_Src[NELEM];
__device__ float g_W[4u * EMB * EMB];
__device__ float g_Q[NELEM];
__device__ float g_K[NELEM];
__device__ float g_Vt[NELEM];                        // [B][EMB][TSEQ]
__device__ float g_S[(size_t)BATCH * TSEQ * TSEQ];   // scores -> P in place
__device__ float g_O[NELEM];

// ---------------- helpers --------------------------------------------------
__device__ __forceinline__ uint32_t smem_u32(const void* p) {
    uint32_t a;
    asm("{ .reg .u64 t; cvta.to.shared.u64 t, %1; cvt.u32.u64 %0, t; }" : "=r"(a) : "l"(p));
    return a;
}
__device__ __forceinline__ float tf32r(float x) {
    uint32_t u;
    asm("cvt.rna.tf32.f32 %0, %1;" : "=r"(u) : "f"(x));
    return __uint_as_float(u);
}
#define CP_ASYNC16(dst, src) \
    asm volatile("cp.async.cg.shared.global [%0], [%1], 16;" :: "r"(dst), "l"(src) : "memory")
#define CP_COMMIT() asm volatile("cp.async.commit_group;" ::: "memory")
#define CP_WAIT0()  asm volatile("cp.async.wait_group 0;" ::: "memory")

#define MMA_TF32(c, a, b) \
    asm volatile("mma.sync.aligned.m16n8k8.row.col.f32.tf32.tf32.f32 " \
        "{%0,%1,%2,%3}, {%4,%5,%6,%7}, {%8,%9}, {%0,%1,%2,%3};" \
        : "+f"((c)[0]), "+f"((c)[1]), "+f"((c)[2]), "+f"((c)[3]) \
        : "r"((a)[0]), "r"((a)[1]), "r"((a)[2]), "r"((a)[3]), "r"((b)[0]), "r"((b)[1]))

// ---------------------------------------------------------------------------
// tf32 GEMM (all-NT): C[M,N] = alpha * A[M,K] @ B[N,K]^T (+ bias[N])
// A,B stored with k-dim permuted by p8. BM=128 BN=128 BK=32, 256 threads =
// 8 warps (2 M x 4 N), warp tile 64x32. 2-stage cp.async, prefetch dist 1,
// one __syncthreads per iteration, 2 CTAs/SM. Rows padded to 40 floats.
// MODE 0: fp32 out (true cols). MODE 1: tf32-rounded out, cols p8-permuted.
// MODE 2: rounded + transposed (Vt[b][col][p8(tok)]).
// ---------------------------------------------------------------------------
#define BM 128
#define BN 128
#define BK 32
#define ROWW 40
#define STG_FLOATS ((BM + BN) * ROWW)   // 10240
#define STG_BYTES  (STG_FLOATS * 4)     // 40960
#define GEMM_SMEM  (2 * STG_BYTES)      // 81920

template <int MODE, bool HAS_BIAS>
__global__ __launch_bounds__(256, 2)
void tf32_gemm(const float* __restrict__ A, const float* __restrict__ B,
               const float* __restrict__ bias, float* __restrict__ C,
               int M, int N, int K, float alpha,
               size_t sA, size_t sB, size_t sC)
{
    extern __shared__ float sm[];
    const uint32_t sb = smem_u32(sm);

    const int tid  = threadIdx.x;
    const int wid  = tid >> 5, lane = tid & 31;
    const int g    = lane >> 2, t4 = lane & 3;
    const int wm   = wid & 1,  wn = wid >> 1;

    const int m0 = blockIdx.y * BM;
    const int n0 = blockIdx.x * BN;
    A += (size_t)blockIdx.z * sA + (size_t)m0 * K;
    B += (size_t)blockIdx.z * sB + (size_t)n0 * K;

    auto load_stage = [&](int kt, int s) {
        const uint32_t st = sb + s * STG_BYTES;
        const int k0 = kt * BK;
#pragma unroll
        for (int i = 0; i < 4; i++) {          // A: 128 rows x 8 chunks
            int id = tid + i * 256, r = id >> 3, c = id & 7;
            CP_ASYNC16(st + (r * ROWW + c * 4) * 4, A + (size_t)r * K + k0 + c * 4);
        }
#pragma unroll
        for (int i = 0; i < 4; i++) {          // B: 128 rows x 8 chunks
            int id = tid + i * 256, r = id >> 3, c = id & 7;
            CP_ASYNC16(st + (BM * ROWW + r * ROWW + c * 4) * 4,
                       B + (size_t)r * K + k0 + c * 4);
        }
        CP_COMMIT();
    };

    // fragment base pointers (k-permuted layout: word 2*t4 holds k=t4,t4+4)
    const float* aBase = sm + (wm * 64 + g) * ROWW + 2 * t4;
    const float* bBase = sm + BM * ROWW + (wn * 32 + g) * ROWW + 2 * t4;

    float acc[4][4][4];
#pragma unroll
    for (int mi = 0; mi < 4; mi++)
#pragma unroll
        for (int ni = 0; ni < 4; ni++)
#pragma unroll
            for (int r = 0; r < 4; r++) acc[mi][ni][r] = 0.0f;

    const int KT = K / BK;
    load_stage(0, 0);

    for (int kt = 0; kt < KT; kt++) {
        CP_WAIT0();
        __syncthreads();
        // stage (kt+1)%2 was last read at iter kt-1; the barrier above
        // ordered those reads -> safe to overwrite now, overlapping MMA(kt).
        if (kt + 1 < KT) load_stage(kt + 1, (kt + 1) & 1);

        const float* As = aBase + (kt & 1) * STG_FLOATS;
        const float* Bs = bBase + (kt & 1) * STG_FLOATS;

#pragma unroll
        for (int ks = 0; ks < 4; ks++) {
            uint32_t af[4][4], bf[4][2];
#pragma unroll
            for (int mi = 0; mi < 4; mi++) {
                float2 lo = *reinterpret_cast<const float2*>(As + mi * 16 * ROWW + ks * 8);
                float2 hi = *reinterpret_cast<const float2*>(As + mi * 16 * ROWW + 8 * ROWW + ks * 8);
                af[mi][0] = __float_as_uint(lo.x);
                af[mi][1] = __float_as_uint(hi.x);
                af[mi][2] = __float_as_uint(lo.y);
                af[mi][3] = __float_as_uint(hi.y);
            }
#pragma unroll
            for (int ni = 0; ni < 4; ni++) {
                float2 b = *reinterpret_cast<const float2*>(Bs + ni * 8 * ROWW + ks * 8);
                bf[ni][0] = __float_as_uint(b.x);
                bf[ni][1] = __float_as_uint(b.y);
            }
#pragma unroll
            for (int mi = 0; mi < 4; mi++)
#pragma unroll
                for (int ni = 0; ni < 4; ni++)
                    MMA_TF32(acc[mi][ni], af[mi], bf[ni]);
        }
    }

    // ---- epilogue ----
    if (MODE == 2) {
        // transposed + rounded: Vt[b][col][p8(tok)]
        float* Cb = C + (size_t)(m0 / TSEQ) * EMB * TSEQ;
        const int pg = ((g & 3) << 1) | (g >> 2);
        const int tokbase = (m0 % TSEQ) + wm * 64 + pg;
#pragma unroll
        for (int mi = 0; mi < 4; mi++) {
            const int tok = tokbase + mi * 16;
#pragma unroll
            for (int ni = 0; ni < 4; ni++) {
                const int col = n0 + wn * 32 + ni * 8 + t4 * 2;
                float b0 = HAS_BIAS ? __ldg(bias + col)     : 0.0f;
                float b1 = HAS_BIAS ? __ldg(bias + col + 1) : 0.0f;
                Cb[(size_t)col * TSEQ + tok]           = tf32r(acc[mi][ni][0] * alpha + b0);
                Cb[(size_t)(col + 1) * TSEQ + tok]     = tf32r(acc[mi][ni][1] * alpha + b1);
                Cb[(size_t)col * TSEQ + tok + 8]       = tf32r(acc[mi][ni][2] * alpha + b0);
                Cb[(size_t)(col + 1) * TSEQ + tok + 8] = tf32r(acc[mi][ni][3] * alpha + b1);
            }
        }
    } else if (MODE == 1) {
        // rounded out, columns stored p8-permuted (they are a k-dim downstream)
        C += (size_t)blockIdx.z * sC;
        const int q0 = ((2 * t4 & 3) << 1) | ((2 * t4) >> 2);
        const int q1 = (((2 * t4 + 1) & 3) << 1) | ((2 * t4 + 1) >> 2);
#pragma unroll
        for (int mi = 0; mi < 4; mi++) {
            const int row = m0 + wm * 64 + mi * 16 + g;
#pragma unroll
            for (int ni = 0; ni < 4; ni++) {
                const int colb = n0 + wn * 32 + ni * 8;
                float b0 = HAS_BIAS ? __ldg(bias + colb + 2 * t4)     : 0.0f;
                float b1 = HAS_BIAS ? __ldg(bias + colb + 2 * t4 + 1) : 0.0f;
                C[(size_t)row * N + colb + q0]       = tf32r(acc[mi][ni][0] * alpha + b0);
                C[(size_t)row * N + colb + q1]       = tf32r(acc[mi][ni][1] * alpha + b1);
                C[(size_t)(row + 8) * N + colb + q0] = tf32r(acc[mi][ni][2] * alpha + b0);
                C[(size_t)(row + 8) * N + colb + q1] = tf32r(acc[mi][ni][3] * alpha + b1);
            }
        }
    } else {
        // MODE 0: plain fp32, true column order
        C += (size_t)blockIdx.z * sC;
#pragma unroll
        for (int mi = 0; mi < 4; mi++) {
            const int row = m0 + wm * 64 + mi * 16 + g;
#pragma unroll
            for (int ni = 0; ni < 4; ni++) {
                const int col = n0 + wn * 32 + ni * 8 + t4 * 2;
                float b0 = HAS_BIAS ? __ldg(bias + col)     : 0.0f;
                float b1 = HAS_BIAS ? __ldg(bias + col + 1) : 0.0f;
                float f0 = acc[mi][ni][0] * alpha + b0;
                float f1 = acc[mi][ni][1] * alpha + b1;
                float f2 = acc[mi][ni][2] * alpha + b0;
                float f3 = acc[mi][ni][3] * alpha + b1;
                *reinterpret_cast<float2*>(C + (size_t)row * N + col)       = make_float2(f0, f1);
                *reinterpret_cast<float2*>(C + (size_t)(row + 8) * N + col) = make_float2(f2, f3);
            }
        }
    }
}

// ---------------------------------------------------------------------------
// rounding passes: tf32-round AND k-permute (8 elements per thread)
// out positions within 8-block: [e0,e4,e1,e5,e2,e6,e3,e7]
// ---------------------------------------------------------------------------
__device__ __forceinline__ void round_perm8(float4 i0, float4 i1,
                                            float4& o0, float4& o1)
{
    o0 = make_float4(tf32r(i0.x), tf32r(i1.x), tf32r(i0.y), tf32r(i1.y));
    o1 = make_float4(tf32r(i0.z), tf32r(i1.z), tf32r(i0.w), tf32r(i1.w));
}

__global__ void round_act_kernel(const float4* __restrict__ a, float4* __restrict__ ya,
                                 const float4* __restrict__ b, float4* __restrict__ yb,
                                 int n8)
{
    int i = blockIdx.x * blockDim.x + threadIdx.x;
    if (i >= n8) return;
    const float4* x = blockIdx.y ? b : a;
    float4*       y = blockIdx.y ? yb : ya;
    float4 o0, o1;
    round_perm8(x[2 * i], x[2 * i + 1], o0, o1);
    y[2 * i] = o0; y[2 * i + 1] = o1;
}

__global__ void round_w_kernel(const float4* __restrict__ w0, const float4* __restrict__ w1,
                               const float4* __restrict__ w2, const float4* __restrict__ w3,
                               float4* __restrict__ y, int n8)
{
    int i = blockIdx.x * blockDim.x + threadIdx.x;
    if (i >= n8) return;
    const float4* src = (blockIdx.y == 0) ? w0 : (blockIdx.y == 1) ? w1
                      : (blockIdx.y == 2) ? w2 : w3;
    float4 o0, o1;
    round_perm8(src[2 * i], src[2 * i + 1], o0, o1);
    y[(size_t)blockIdx.y * 2 * n8 + 2 * i]     = o0;
    y[(size_t)blockIdx.y * 2 * n8 + 2 * i + 1] = o1;
}

// ---------------------------------------------------------------------------
// softmax over 2048-length rows (in place): reads true-order S, writes
// tf32-rounded P with k-permuted columns. 8 elements per thread.
// ---------------------------------------------------------------------------
__device__ __forceinline__ float blk_red_max(float v) {
    __shared__ float sh[8]; __shared__ float res;
    const int lane = threadIdx.x & 31, warp = threadIdx.x >> 5;
#pragma unroll
    for (int o = 16; o > 0; o >>= 1) v = fmaxf(v, __shfl_xor_sync(0xffffffffu, v, o));
    if (lane == 0) sh[warp] = v;
    __syncthreads();
    if (warp == 0) {
        float w = (lane < 8) ? sh[lane] : -3.0e38f;
#pragma unroll
        for (int o = 4; o > 0; o >>= 1) w = fmaxf(w, __shfl_xor_sync(0xffffffffu, w, o));
        if (lane == 0) res = w;
    }
    __syncthreads();
    return res;
}
__device__ __forceinline__ float blk_red_sum(float v) {
    __shared__ float sh[8]; __shared__ float res;
    const int lane = threadIdx.x & 31, warp = threadIdx.x >> 5;
#pragma unroll
    for (int o = 16; o > 0; o >>= 1) v += __shfl_xor_sync(0xffffffffu, v, o);
    if (lane == 0) sh[warp] = v;
    __syncthreads();
    if (warp == 0) {
        float w = (lane < 8) ? sh[lane] : 0.0f;
#pragma unroll
        for (int o = 4; o > 0; o >>= 1) w += __shfl_xor_sync(0xffffffffu, w, o);
        if (lane == 0) res = w;
    }
    __syncthreads();
    return res;
}

__global__ __launch_bounds__(256)
void softmax_kernel(float* __restrict__ S)
{
    float4* row = reinterpret_cast<float4*>(S + (size_t)blockIdx.x * TSEQ);
    const int t = threadIdx.x;

    float4 v0 = row[2 * t];       // elements 8t .. 8t+3
    float4 v1 = row[2 * t + 1];   // elements 8t+4 .. 8t+7

    float mx = fmaxf(fmaxf(fmaxf(v0.x, v0.y), fmaxf(v0.z, v0.w)),
                     fmaxf(fmaxf(v1.x, v1.y), fmaxf(v1.z, v1.w)));
    mx = blk_red_max(mx);

    v0.x = __expf(v0.x - mx); v0.y = __expf(v0.y - mx);
    v0.z = __expf(v0.z - mx); v0.w = __expf(v0.w - mx);
    v1.x = __expf(v1.x - mx); v1.y = __expf(v1.y - mx);
    v1.z = __expf(v1.z - mx); v1.w = __expf(v1.w - mx);

    float s = (v0.x + v0.y + v0.z + v0.w) + (v1.x + v1.y + v1.z + v1.w);
    s = blk_red_sum(s);
    const float inv = 1.0f / s;

    v0.x *= inv; v0.y *= inv; v0.z *= inv; v0.w *= inv;
    v1.x *= inv; v1.y *= inv; v1.z *= inv; v1.w *= inv;

    float4 o0, o1;
    round_perm8(v0, v1, o0, o1);
    row[2 * t]     = o0;
    row[2 * t + 1] = o1;
}

// ---------------------------------------------------------------------------
extern "C" void kernel_launch(void* const* d_in, const int* in_sizes, int n_in,
                              void* d_out, int out_size)
{
    const float* target = (const float*)d_in[0];
    const float* source = (const float*)d_in[1];
    const float* Wq = (const float*)d_in[2];
    const float* bq = (const float*)d_in[3];
    const float* Wk = (const float*)d_in[4];
    const float* bk = (const float*)d_in[5];
    const float* Wv = (const float*)d_in[6];
    const float* bv = (const float*)d_in[7];
    const float* Wo = (const float*)d_in[8];
    const float* bo = (const float*)d_in[9];
    float* out = (float*)d_out;

    float *T, *Src, *W, *Q, *Kb, *Vt, *S, *O;
    cudaGetSymbolAddress((void**)&T,   g_T);
    cudaGetSymbolAddress((void**)&Src, g_Src);
    cudaGetSymbolAddress((void**)&W,   g_W);
    cudaGetSymbolAddress((void**)&Q,   g_Q);
    cudaGetSymbolAddress((void**)&Kb,  g_K);
    cudaGetSymbolAddress((void**)&Vt,  g_Vt);
    cudaGetSymbolAddress((void**)&S,   g_S);
    cudaGetSymbolAddress((void**)&O,   g_O);

    cudaFuncSetAttribute(tf32_gemm<0, false>, cudaFuncAttributeMaxDynamicSharedMemorySize, GEMM_SMEM);
    cudaFuncSetAttribute(tf32_gemm<0, true>,  cudaFuncAttributeMaxDynamicSharedMemorySize, GEMM_SMEM);
    cudaFuncSetAttribute(tf32_gemm<1, false>, cudaFuncAttributeMaxDynamicSharedMemorySize, GEMM_SMEM);
    cudaFuncSetAttribute(tf32_gemm<1, true>,  cudaFuncAttributeMaxDynamicSharedMemorySize, GEMM_SMEM);
    cudaFuncSetAttribute(tf32_gemm<2, true>,  cudaFuncAttributeMaxDynamicSharedMemorySize, GEMM_SMEM);

    // launch 0: round+perm both activations; launch 1: round+perm 4 weights
    {
        dim3 ga((unsigned)(NELEM / 8 / 256), 2, 1);
        round_act_kernel<<<ga, 256>>>((const float4*)target, (float4*)T,
                                      (const float4*)source, (float4*)Src,
                                      (int)(NELEM / 8));
        dim3 gw((unsigned)(EMB * EMB / 8 / 256), 4, 1);
        round_w_kernel<<<gw, 256>>>((const float4*)Wq, (const float4*)Wk,
                                    (const float4*)Wv, (const float4*)Wo,
                                    (float4*)W, EMB * EMB / 8);
    }

    const float scale = 1.0f / 32.0f;  // 1/sqrt(1024)

    // launches 2-4: projections
    {
        dim3 grd(EMB / BN, MTOT / BM, 1);
        tf32_gemm<1, true><<<grd, 256, GEMM_SMEM>>>(T,   W + 0u * EMB * EMB, bq, Q,
                                                    MTOT, EMB, EMB, 1.0f, 0, 0, 0);
        tf32_gemm<1, true><<<grd, 256, GEMM_SMEM>>>(Src, W + 1u * EMB * EMB, bk, Kb,
                                                    MTOT, EMB, EMB, 1.0f, 0, 0, 0);
        tf32_gemm<2, true><<<grd, 256, GEMM_SMEM>>>(Src, W + 2u * EMB * EMB, bv, Vt,
                                                    MTOT, EMB, EMB, 1.0f, 0, 0, 0);
    }

    // launch 5 (ncu -s 5 -c 1 captures this): S = Q @ K^T / 32
    {
        dim3 grd(TSEQ / BN, TSEQ / BM, BATCH);
        tf32_gemm<0, false><<<grd, 256, GEMM_SMEM>>>(Q, Kb, nullptr, S,
            TSEQ, TSEQ, EMB, scale,
            (size_t)TSEQ * EMB, (size_t)TSEQ * EMB, (size_t)TSEQ * TSEQ);
    }

    // P = softmax(S) in place (rounded + k-permuted)
    softmax_kernel<<<BATCH * TSEQ, 256>>>(S);

    // O = P @ Vt^T (batched, K=2048)
    {
        dim3 grd(EMB / BN, TSEQ / BM, BATCH);
        tf32_gemm<1, false><<<grd, 256, GEMM_SMEM>>>(S, Vt, nullptr, O,
            TSEQ, EMB, TSEQ, 1.0f,
            (size_t)TSEQ * TSEQ, (size_t)EMB * TSEQ, (size_t)TSEQ * EMB);
    }

    // out = O @ Wo^T + bo (fp32, true order)
    {
        dim3 grd(EMB / BN, MTOT / BM, 1);
        tf32_gemm<0, true><<<grd, 256, GEMM_SMEM>>>(O, W + 3u * EMB * EMB, bo, out,
                                                    MTOT, EMB, EMB, 1.0f, 0, 0, 0);
    }
}